// round 15
// baseline (speedup 1.0000x reference)
#include <cuda_runtime.h>
#include <cuda_bf16.h>
#include <cuda_fp16.h>
#include <stdint.h>
#include <math.h>

#define BB 4
#define TT 1024
#define CC 2048
#define HH 16
#define DD 128

typedef unsigned long long u64;

__device__ __forceinline__ uint32_t smem_u32(const void* p) {
    uint32_t a;
    asm("{ .reg .u64 t; cvta.to.shared.u64 t, %1; cvt.u32.u64 %0, t; }" : "=r"(a) : "l"(p));
    return a;
}

// ===========================================================================
// HMMA path: ldmatrix + mma.sync + cp.async (sm_80 baseline ISA), fp16 kind
// ===========================================================================
#define LDSM_X4(r, addr) \
    asm volatile("ldmatrix.sync.aligned.m8n8.x4.shared.b16 {%0,%1,%2,%3}, [%4];" \
        : "=r"((r)[0]), "=r"((r)[1]), "=r"((r)[2]), "=r"((r)[3]) : "r"(addr))

#define LDSM_X4_T(r, addr) \
    asm volatile("ldmatrix.sync.aligned.m8n8.x4.trans.shared.b16 {%0,%1,%2,%3}, [%4];" \
        : "=r"((r)[0]), "=r"((r)[1]), "=r"((r)[2]), "=r"((r)[3]) : "r"(addr))

#define MMA_FP16(d, a, b) \
    asm volatile("mma.sync.aligned.m16n8k16.row.col.f32.f16.f16.f32 " \
        "{%0,%1,%2,%3}, {%4,%5,%6,%7}, {%8,%9}, {%0,%1,%2,%3};" \
        : "+f"((d)[0]), "+f"((d)[1]), "+f"((d)[2]), "+f"((d)[3]) \
        : "r"((a)[0]), "r"((a)[1]), "r"((a)[2]), "r"((a)[3]), \
          "r"((b)[0]), "r"((b)[1]))

#define CP_ASYNC16(saddr, gptr) \
    asm volatile("cp.async.cg.shared.global [%0], [%1], 16;" \
        :: "r"(saddr), "l"(gptr) : "memory")
#define CP_COMMIT() asm volatile("cp.async.commit_group;" ::: "memory")
#define CP_WAIT1()  asm volatile("cp.async.wait_group 1;" ::: "memory")
#define CP_WAIT0()  asm volatile("cp.async.wait_group 0;" ::: "memory")

// ===========================================================================
// Scratch (device globals — no allocation allowed)
// ===========================================================================
__device__ float g_q[8388608];   // (B,H,T,D) fp32 (pre-RoPE)
__device__ float g_k[8388608];
__device__ float g_y[8388608];   // (B,T,C)
__device__ float g_u[196608];    // (B,T,48)
__device__ float g_uo[65536];    // (B,T,16)
__device__ __align__(16) __half g_xhi[8388608];
__device__ __align__(16) __half g_xlo[8388608];
__device__ __align__(16) __half g_yhi[8388608];
__device__ __align__(16) __half g_ylo[8388608];
__device__ __align__(16) __half g_whi[16777216];  // [q|k|v|o][2048][2048]
__device__ __align__(16) __half g_qhi[8388608];
__device__ __align__(16) __half g_qlo[8388608];
__device__ __align__(16) __half g_khi[8388608];
__device__ __align__(16) __half g_vhi[8388608];

// ===========================================================================
// fp32 -> fp16 split helpers
// ===========================================================================
__device__ __forceinline__ void split4h(float4 v, __half* hi, __half* lo) {
    __half h0 = __float2half_rn(v.x), h1 = __float2half_rn(v.y);
    __half h2 = __float2half_rn(v.z), h3 = __float2half_rn(v.w);
    __half l0 = __float2half_rn(v.x - __half2float(h0));
    __half l1 = __float2half_rn(v.y - __half2float(h1));
    __half l2 = __float2half_rn(v.z - __half2float(h2));
    __half l3 = __float2half_rn(v.w - __half2float(h3));
    __half2 p;
    p.x = h0; p.y = h1; *(__half2*)(hi)     = p;
    p.x = h2; p.y = h3; *(__half2*)(hi + 2) = p;
    p.x = l0; p.y = l1; *(__half2*)(lo)     = p;
    p.x = l2; p.y = l3; *(__half2*)(lo + 2) = p;
}
__device__ __forceinline__ void cvt4h(float4 v, __half* hi) {
    __half2 p;
    p.x = __float2half_rn(v.x); p.y = __float2half_rn(v.y);
    *(__half2*)(hi) = p;
    p.x = __float2half_rn(v.z); p.y = __float2half_rn(v.w);
    *(__half2*)(hi + 2) = p;
}

// split x -> g_xhi/g_xlo
__global__ void split_x_kernel(const float* __restrict__ x)
{
    int i = (blockIdx.x * 256 + threadIdx.x) * 4;
    split4h(*(const float4*)(x + i), g_xhi + i, g_xlo + i);
}

// W: hi only (the A-side carries the split)
__global__ void split_w_kernel(const float* __restrict__ Wq, const float* __restrict__ Wk,
                               const float* __restrict__ Wv, const float* __restrict__ Wo)
{
    int j = blockIdx.y;
    const float* src = (j == 0) ? Wq : (j == 1) ? Wk : (j == 2) ? Wv : Wo;
    size_t base = (size_t)j * 4194304;
    int i = (blockIdx.x * 256 + threadIdx.x) * 4;
    cvt4h(*(const float4*)(src + i), g_whi + base + i);
}

// ===========================================================================
// Fused RoPE + split: read q,k fp32, rotate, write qhi/qlo/khi (one pass).
// ===========================================================================
__global__ void rope_split_qk_kernel()
{
    int idx = blockIdx.x * 256 + threadIdx.x;
    if (idx >= BB * HH * TT * 64) return;
    int j  = idx & 63;
    int t  = (idx >> 6) & 1023;
    int bh = idx >> 16;
    float inv = exp2f(-(float)j * (13.2877123795f / 64.0f));
    float ang = (float)t * inv;
    float c, s;
    sincosf(ang, &s, &c);
    size_t base = ((size_t)bh * TT + t) * DD + j;

    float q1 = g_q[base], q2 = g_q[base + 64];
    float qa = q1 * c - q2 * s;
    float qb = q2 * c + q1 * s;
    __half ha = __float2half_rn(qa), hb = __float2half_rn(qb);
    g_qhi[base]      = ha;
    g_qhi[base + 64] = hb;
    g_qlo[base]      = __float2half_rn(qa - __half2float(ha));
    g_qlo[base + 64] = __float2half_rn(qb - __half2float(hb));

    float k1 = g_k[base], k2 = g_k[base + 64];
    g_khi[base]      = __float2half_rn(k1 * c - k2 * s);
    g_khi[base + 64] = __float2half_rn(k2 * c + k1 * s);
}

// ===========================================================================
// LoRA left factor. mode 0: U = x @ dA^T (48 cols), mode 1: Uo = y @ doA^T
// ===========================================================================
__global__ void lora_u_kernel(const float* __restrict__ x,
                              const float* __restrict__ delta, int mode)
{
    int bt = blockIdx.x;
    int b  = bt >> 10;
    const float* src  = (mode == 0) ? x : (const float*)g_y;
    const float* xrow = src + (size_t)bt * CC;
    float* dst = (mode == 0) ? g_u : g_uo;
    int nOut   = (mode == 0) ? 48 : 16;

    int lane = threadIdx.x & 31, w = threadIdx.x >> 5;
    for (int j = w; j < nOut; j += 8) {
        int row = (mode == 0) ? ((j >> 4) * 32 + (j & 15)) : (96 + j);
        const float* arow = delta + ((size_t)b * 128 + row) * CC;
        float s = 0.f;
        for (int i = lane * 4; i < CC; i += 128) {
            float4 xv = *(const float4*)(xrow + i);
            float4 av = *(const float4*)(arow + i);
            s += xv.x * av.x + xv.y * av.y + xv.z * av.z + xv.w * av.w;
        }
        #pragma unroll
        for (int o = 16; o; o >>= 1) s += __shfl_xor_sync(0xffffffffu, s, o);
        if (lane == 0) dst[(size_t)bt * nOut + j] = s;
    }
}

// ===========================================================================
// fp16x2 GEMM on mma.sync + cp.async 3-stage pipeline.
// out = Ah*Bh + Al*Bh. Tile 128x128, K-stage 32, 16 warps (4m x 4n), 512 thr.
// mode 0: QKV; q,k -> fp32 head layout, v -> g_vhi (fp16, bit-identical to
//         old fp32-store->cvt path). mode 1: O -> outO.
// ===========================================================================
#define MMH_STAGE 30720
#define MMH_SMEM  (3 * MMH_STAGE)

__global__ __launch_bounds__(512, 1)
void mmh_kernel(const float* __restrict__ delta, int mode, float* __restrict__ outO)
{
    extern __shared__ __align__(16) char sm[];
    const int tid = threadIdx.x, lane = tid & 31, wid = tid >> 5;
    const int wm = wid >> 2, wn = wid & 3;
    const int b = blockIdx.z, mt = blockIdx.y, nt = blockIdx.x;
    const int m0 = mt * 128, nbase = nt * 128;
    const int wrow0 = (mode == 0) ? nbase : (6144 + nbase);
    const size_t arow0 = (size_t)b * 1024 + m0;

    const __half* Ahi = (mode == 0) ? g_xhi : g_yhi;
    const __half* Alo = (mode == 0) ? g_xlo : g_ylo;
    const float* Uv = (mode == 0) ? g_u : g_uo;

    const int lrow = tid >> 2, seg = tid & 3;
    const __half* gAh = Ahi + (arow0 + lrow) * 2048 + seg * 8;
    const __half* gAl = Alo + (arow0 + lrow) * 2048 + seg * 8;
    const __half* gBh = g_whi + (size_t)(wrow0 + lrow) * 2048 + seg * 8;
    const uint32_t so = (uint32_t)lrow * 80 + seg * 16;
    const uint32_t sb = smem_u32(sm);

    float acc[2][4][4];
    #pragma unroll
    for (int mi = 0; mi < 2; mi++)
        #pragma unroll
        for (int ni = 0; ni < 4; ni++)
            #pragma unroll
            for (int e = 0; e < 4; e++) acc[mi][ni][e] = 0.f;

    #define MMH_ISSUE(sbase, kt) do { \
        int kk = (kt) * 32; \
        CP_ASYNC16((sbase) + so,         gAh + kk); \
        CP_ASYNC16((sbase) + 10240 + so, gAl + kk); \
        CP_ASYNC16((sbase) + 20480 + so, gBh + kk); \
    } while (0)

    MMH_ISSUE(sb, 0);              CP_COMMIT();
    MMH_ISSUE(sb + MMH_STAGE, 1);  CP_COMMIT();

    const uint32_t aRowBase = (uint32_t)(wm * 32 + (lane & 15)) * 80 + (lane >> 4) * 16;
    const uint32_t bRowBase = (uint32_t)(wn * 32 + (lane & 15)) * 80 + (lane >> 4) * 16;

    int buf = 0, nxt = 2;
    for (int kt = 0; kt < 64; kt++) {
        CP_WAIT1();
        __syncthreads();
        if (kt < 62) MMH_ISSUE(sb + nxt * MMH_STAGE, kt + 2);
        CP_COMMIT();

        uint32_t sA = sb + buf * MMH_STAGE;
        uint32_t sB = sA + 20480;
        #pragma unroll
        for (int ks = 0; ks < 2; ks++) {
            uint32_t ah[2][4], al[2][4], bh[4][2];
            #pragma unroll
            for (int mi = 0; mi < 2; mi++) {
                uint32_t ad = sA + aRowBase + mi * (16 * 80) + ks * 32;
                LDSM_X4(ah[mi], ad);
                LDSM_X4(al[mi], ad + 10240);
            }
            #pragma unroll
            for (int g = 0; g < 2; g++) {
                uint32_t bd = sB + bRowBase + g * (16 * 80) + ks * 32;
                uint32_t t[4];
                LDSM_X4(t, bd);
                bh[g * 2][0] = t[0];  bh[g * 2][1] = t[2];
                bh[g * 2 + 1][0] = t[1]; bh[g * 2 + 1][1] = t[3];
            }
            #pragma unroll
            for (int mi = 0; mi < 2; mi++)
                #pragma unroll
                for (int ni = 0; ni < 4; ni++) {
                    MMA_FP16(acc[mi][ni], ah[mi], bh[ni]);
                    MMA_FP16(acc[mi][ni], al[mi], bh[ni]);
                }
        }
        buf = (buf == 2) ? 0 : buf + 1;
        nxt = (nxt == 2) ? 0 : nxt + 1;
    }
    CP_WAIT0();
    __syncthreads();

    // ---- LoRA epilogue + writeback ----
    float* sU  = (float*)sm;               // [128][17]
    float* sDb = (float*)(sm + 12288);     // [16][136]
    const int seg2    = (mode == 0) ? (nbase >> 11) : 3;
    const int ncol0   = (mode == 0) ? (nbase & 2047) : nbase;
    const int dbrow   = (mode == 0) ? (seg2 * 32 + 16) : 112;
    const int ustride = (mode == 0) ? 48 : 16;
    const int uoff    = (mode == 0) ? seg2 * 16 : 0;

    if (tid < 128) {
        const float* up = Uv + ((size_t)b * 1024 + m0 + tid) * ustride + uoff;
        #pragma unroll
        for (int i = 0; i < 4; i++) {
            float4 v = *(const float4*)(up + i * 4);
            sU[tid * 17 + i * 4 + 0] = v.x;
            sU[tid * 17 + i * 4 + 1] = v.y;
            sU[tid * 17 + i * 4 + 2] = v.z;
            sU[tid * 17 + i * 4 + 3] = v.w;
        }
    }
    {
        int r = tid >> 5, c4 = (tid & 31) * 4;
        float4 v = *(const float4*)(delta + ((size_t)b * 128 + dbrow + r) * 2048 + ncol0 + c4);
        *(float4*)(sDb + r * 136 + c4) = v;
    }
    __syncthreads();

    const int trow = lane >> 2;
    const int tcol = (lane & 3) * 2;

    #pragma unroll
    for (int mi = 0; mi < 2; mi++) {
        int lr0 = wm * 32 + mi * 16 + trow;
        int lr1 = lr0 + 8;
        #pragma unroll
        for (int r = 0; r < 16; r++) {
            float u0 = sU[lr0 * 17 + r];
            float u1 = sU[lr1 * 17 + r];
            #pragma unroll
            for (int ni = 0; ni < 4; ni++) {
                int c = wn * 32 + ni * 8 + tcol;
                float d0 = sDb[r * 136 + c];
                float d1 = sDb[r * 136 + c + 1];
                acc[mi][ni][0] += u0 * d0;
                acc[mi][ni][1] += u0 * d1;
                acc[mi][ni][2] += u1 * d0;
                acc[mi][ni][3] += u1 * d1;
            }
        }
        #pragma unroll
        for (int ni = 0; ni < 4; ni++) {
            int c = wn * 32 + ni * 8 + tcol;
            if (mode == 0) {
                int h = ncol0 >> 7;
                size_t hb = (((size_t)b * 16 + h) * 1024 + m0) * 128;
                if (seg2 == 2) {
                    __half2 h0, h1;
                    h0.x = __float2half_rn(acc[mi][ni][0]);
                    h0.y = __float2half_rn(acc[mi][ni][1]);
                    h1.x = __float2half_rn(acc[mi][ni][2]);
                    h1.y = __float2half_rn(acc[mi][ni][3]);
                    *(__half2*)(g_vhi + hb + (size_t)lr0 * 128 + c) = h0;
                    *(__half2*)(g_vhi + hb + (size_t)lr1 * 128 + c) = h1;
                } else {
                    float* dst = ((seg2 == 0) ? g_q : g_k) + hb;
                    *(float2*)(dst + (size_t)lr0 * 128 + c) = make_float2(acc[mi][ni][0], acc[mi][ni][1]);
                    *(float2*)(dst + (size_t)lr1 * 128 + c) = make_float2(acc[mi][ni][2], acc[mi][ni][3]);
                }
            } else {
                float* dst = outO + ((size_t)b * 1024 + m0) * 2048 + nbase;
                *(float2*)(dst + (size_t)lr0 * 2048 + c) = make_float2(acc[mi][ni][0], acc[mi][ni][1]);
                *(float2*)(dst + (size_t)lr1 * 2048 + c) = make_float2(acc[mi][ni][2], acc[mi][ni][3]);
            }
        }
    }
}

// ===========================================================================
// HMMA flash attention, fp16x2. Writes y fp32 + yhi/ylo (fused split).
// ===========================================================================
#define AT_PITCH 272
#define AT_QH 0
#define AT_QL 34816
#define AT_KH 69632
#define AT_VH 104448
#define AT_SMEM 139264

__device__ __forceinline__ void split_pack_h(float x, float y, uint32_t& hi, uint32_t& lo)
{
    __half hx = __float2half_rn(x), hy = __float2half_rn(y);
    __half lx = __float2half_rn(x - __half2float(hx));
    __half ly = __float2half_rn(y - __half2float(hy));
    __half2 h; h.x = hx; h.y = hy;
    __half2 l; l.x = lx; l.y = ly;
    hi = *(uint32_t*)&h;
    lo = *(uint32_t*)&l;
}

__global__ __launch_bounds__(256, 1) void attn_h_kernel()
{
    extern __shared__ __align__(16) char sm[];
    const int tid = threadIdx.x, lane = tid & 31, wid = tid >> 5;
    const int qt = blockIdx.x, bh = blockIdx.y;
    const int q0 = qt * 128;
    const size_t tbase = (size_t)bh * 1024;
    const uint32_t sb = smem_u32(sm);

    #pragma unroll
    for (int i = 0; i < 8; i++) {
        int s = tid + i * 256;
        int row = s >> 4, c = s & 15;
        uint32_t off = (uint32_t)row * AT_PITCH + c * 16;
        size_t g = (tbase + q0 + row) * 128 + c * 8;
        *(uint4*)(sm + AT_QH + off) = *(const uint4*)(g_qhi + g);
        *(uint4*)(sm + AT_QL + off) = *(const uint4*)(g_qlo + g);
    }

    const int gq = lane >> 2, t4 = lane & 3;
    const uint32_t ldRow = (uint32_t)(lane & 15) * AT_PITCH + (lane >> 4) * 16;
    const uint32_t qBase = sb + AT_QH + (uint32_t)(wid * 16) * AT_PITCH + ldRow;

    float o[16][4];
    #pragma unroll
    for (int n = 0; n < 16; n++)
        #pragma unroll
        for (int e = 0; e < 4; e++) o[n][e] = 0.f;
    float mA = -3.0e38f, mB = -3.0e38f, lA = 0.f, lB = 0.f;
    const float scale = 0.08838834764831845f;

    for (int kt = 0; kt < 8; kt++) {
        #pragma unroll
        for (int i = 0; i < 8; i++) {
            int s = tid + i * 256;
            int row = s >> 4, c = s & 15;
            uint32_t off = (uint32_t)row * AT_PITCH + c * 16;
            size_t g = (tbase + kt * 128 + row) * 128 + c * 8;
            *(uint4*)(sm + AT_KH + off) = *(const uint4*)(g_khi + g);
            *(uint4*)(sm + AT_VH + off) = *(const uint4*)(g_vhi + g);
        }
        __syncthreads();

        float s[16][4];
        #pragma unroll
        for (int n = 0; n < 16; n++)
            #pragma unroll
            for (int e = 0; e < 4; e++) s[n][e] = 0.f;

        #pragma unroll
        for (int ks = 0; ks < 8; ks++) {
            uint32_t qh[4], ql[4];
            LDSM_X4(qh, qBase + ks * 32);
            LDSM_X4(ql, qBase + (AT_QL - AT_QH) + ks * 32);
            #pragma unroll
            for (int np = 0; np < 8; np++) {
                uint32_t th[4];
                uint32_t ka = sb + AT_KH + ldRow + np * (16 * AT_PITCH) + ks * 32;
                LDSM_X4(th, ka);
                uint32_t b0h[2] = {th[0], th[2]}, b1h[2] = {th[1], th[3]};
                MMA_FP16(s[2 * np],     qh, b0h);
                MMA_FP16(s[2 * np],     ql, b0h);
                MMA_FP16(s[2 * np + 1], qh, b1h);
                MMA_FP16(s[2 * np + 1], ql, b1h);
            }
        }

        float mxA = -3.0e38f, mxB = -3.0e38f;
        #pragma unroll
        for (int n = 0; n < 16; n++) {
            mxA = fmaxf(mxA, fmaxf(s[n][0], s[n][1]));
            mxB = fmaxf(mxB, fmaxf(s[n][2], s[n][3]));
        }
        mxA = fmaxf(mxA, __shfl_xor_sync(0xffffffffu, mxA, 1));
        mxA = fmaxf(mxA, __shfl_xor_sync(0xffffffffu, mxA, 2));
        mxB = fmaxf(mxB, __shfl_xor_sync(0xffffffffu, mxB, 1));
        mxB = fmaxf(mxB, __shfl_xor_sync(0xffffffffu, mxB, 2));
        float nmA = fmaxf(mA, mxA * scale);
        float nmB = fmaxf(mB, mxB * scale);
        float aA = __expf(mA - nmA), aB = __expf(mB - nmB);
        mA = nmA; mB = nmB;
        float sumA = 0.f, sumB = 0.f;
        #pragma unroll
        for (int n = 0; n < 16; n++) {
            s[n][0] = __expf(s[n][0] * scale - mA); sumA += s[n][0];
            s[n][1] = __expf(s[n][1] * scale - mA); sumA += s[n][1];
            s[n][2] = __expf(s[n][2] * scale - mB); sumB += s[n][2];
            s[n][3] = __expf(s[n][3] * scale - mB); sumB += s[n][3];
        }
        sumA += __shfl_xor_sync(0xffffffffu, sumA, 1);
        sumA += __shfl_xor_sync(0xffffffffu, sumA, 2);
        sumB += __shfl_xor_sync(0xffffffffu, sumB, 1);
        sumB += __shfl_xor_sync(0xffffffffu, sumB, 2);
        lA = lA * aA + sumA;
        lB = lB * aB + sumB;
        #pragma unroll
        for (int n = 0; n < 16; n++) {
            o[n][0] *= aA; o[n][1] *= aA;
            o[n][2] *= aB; o[n][3] *= aB;
        }

        #pragma unroll
        for (int kk = 0; kk < 8; kk++) {
            uint32_t ph[4], pl[4];
            split_pack_h(s[2 * kk][0],     s[2 * kk][1],     ph[0], pl[0]);
            split_pack_h(s[2 * kk][2],     s[2 * kk][3],     ph[1], pl[1]);
            split_pack_h(s[2 * kk + 1][0], s[2 * kk + 1][1], ph[2], pl[2]);
            split_pack_h(s[2 * kk + 1][2], s[2 * kk + 1][3], ph[3], pl[3]);
            #pragma unroll
            for (int np = 0; np < 8; np++) {
                uint32_t tv[4];
                uint32_t va = sb + AT_VH + ldRow + kk * (16 * AT_PITCH) + np * 32;
                LDSM_X4_T(tv, va);
                uint32_t b0[2] = {tv[0], tv[1]}, b1[2] = {tv[2], tv[3]};
                MMA_FP16(o[2 * np],     ph, b0);
                MMA_FP16(o[2 * np],     pl, b0);
                MMA_FP16(o[2 * np + 1], ph, b1);
                MMA_FP16(o[2 * np + 1], pl, b1);
            }
        }
        __syncthreads();
    }

    // ---- normalize + write y fp32 and yhi/ylo (fused split, bit-exact) ----
    int b = bh >> 4, h = bh & 15;
    float iA = 1.f / lA, iB = 1.f / lB;
    int rA = q0 + wid * 16 + gq, rB = rA + 8;
    size_t offA = ((size_t)b * TT + rA) * CC + h * 128;
    size_t offB = ((size_t)b * TT + rB) * CC + h * 128;
    #pragma unroll
    for (int n = 0; n < 16; n++) {
        int d = n * 8 + t4 * 2;
        float a0 = o[n][0] * iA, a1 = o[n][1] * iA;
        float b0 = o[n][2] * iB, b1 = o[n][3] * iB;
        *(float2*)(g_y + offA + d) = make_float2(a0, a1);
        *(float2*)(g_y + offB + d) = make_float2(b0, b1);
        uint32_t hA, lA2, hB, lB2;
        split_pack_h(a0, a1, hA, lA2);
        split_pack_h(b0, b1, hB, lB2);
        *(uint32_t*)(g_yhi + offA + d) = hA;
        *(uint32_t*)(g_ylo + offA + d) = lA2;
        *(uint32_t*)(g_yhi + offB + d) = hB;
        *(uint32_t*)(g_ylo + offB + d) = lB2;
    }
}

// ===========================================================================
extern "C" void kernel_launch(void* const* d_in, const int* in_sizes, int n_in,
                              void* d_out, int out_size)
{
    const float* x     = (const float*)d_in[0];
    const float* delta = (const float*)d_in[1];
    const float* Wq    = (const float*)d_in[2];
    const float* Wk    = (const float*)d_in[3];
    const float* Wv    = (const float*)d_in[4];
    const float* Wo    = (const float*)d_in[5];
    float* out = (float*)d_out;

    cudaFuncSetAttribute(mmh_kernel, cudaFuncAttributeMaxDynamicSharedMemorySize,
                         MMH_SMEM);
    cudaFuncSetAttribute(attn_h_kernel, cudaFuncAttributeMaxDynamicSharedMemorySize,
                         AT_SMEM);

    split_w_kernel<<<dim3(4096, 4), 256>>>(Wq, Wk, Wv, Wo);
    split_x_kernel<<<8192, 256>>>(x);
    lora_u_kernel<<<BB * TT, 256>>>(x, delta, 0);
    mmh_kernel<<<dim3(48, 8, BB), 512, MMH_SMEM>>>(delta, 0, nullptr);
    rope_split_qk_kernel<<<(BB * HH * TT * 64) / 256, 256>>>();
    attn_h_kernel<<<dim3(8, BB * HH), 256, AT_SMEM>>>();
    lora_u_kernel<<<BB * TT, 256>>>(x, delta, 1);
    mmh_kernel<<<dim3(16, 8, BB), 512, MMH_SMEM>>>(delta, 1, out);
}

// round 16
// speedup vs baseline: 1.0525x; 1.0525x over previous
#include <cuda_runtime.h>
#include <cuda_bf16.h>
#include <cuda_fp16.h>
#include <stdint.h>
#include <math.h>

#define BB 4
#define TT 1024
#define CC 2048
#define HH 16
#define DD 128

typedef unsigned long long u64;

__device__ __forceinline__ uint32_t smem_u32(const void* p) {
    uint32_t a;
    asm("{ .reg .u64 t; cvta.to.shared.u64 t, %1; cvt.u32.u64 %0, t; }" : "=r"(a) : "l"(p));
    return a;
}

// ===========================================================================
// HMMA path: ldmatrix + mma.sync + cp.async (sm_80 baseline ISA), fp16 kind
// ===========================================================================
#define LDSM_X4(r, addr) \
    asm volatile("ldmatrix.sync.aligned.m8n8.x4.shared.b16 {%0,%1,%2,%3}, [%4];" \
        : "=r"((r)[0]), "=r"((r)[1]), "=r"((r)[2]), "=r"((r)[3]) : "r"(addr))

#define LDSM_X4_T(r, addr) \
    asm volatile("ldmatrix.sync.aligned.m8n8.x4.trans.shared.b16 {%0,%1,%2,%3}, [%4];" \
        : "=r"((r)[0]), "=r"((r)[1]), "=r"((r)[2]), "=r"((r)[3]) : "r"(addr))

#define MMA_FP16(d, a, b) \
    asm volatile("mma.sync.aligned.m16n8k16.row.col.f32.f16.f16.f32 " \
        "{%0,%1,%2,%3}, {%4,%5,%6,%7}, {%8,%9}, {%0,%1,%2,%3};" \
        : "+f"((d)[0]), "+f"((d)[1]), "+f"((d)[2]), "+f"((d)[3]) \
        : "r"((a)[0]), "r"((a)[1]), "r"((a)[2]), "r"((a)[3]), \
          "r"((b)[0]), "r"((b)[1]))

#define CP_ASYNC16(saddr, gptr) \
    asm volatile("cp.async.cg.shared.global [%0], [%1], 16;" \
        :: "r"(saddr), "l"(gptr) : "memory")
#define CP_COMMIT() asm volatile("cp.async.commit_group;" ::: "memory")
#define CP_WAIT1()  asm volatile("cp.async.wait_group 1;" ::: "memory")
#define CP_WAIT0()  asm volatile("cp.async.wait_group 0;" ::: "memory")

// ===========================================================================
// Scratch (device globals — no allocation allowed)
// ===========================================================================
__device__ float g_q[8388608];   // (B,H,T,D) fp32 (pre-RoPE)
__device__ float g_k[8388608];
__device__ float g_v[8388608];
__device__ float g_y[8388608];   // (B,T,C)
__device__ float g_u[196608];    // (B,T,48)
__device__ float g_uo[65536];    // (B,T,16)
__device__ __align__(16) __half g_xhi[8388608];
__device__ __align__(16) __half g_xlo[8388608];
__device__ __align__(16) __half g_yhi[8388608];
__device__ __align__(16) __half g_ylo[8388608];
__device__ __align__(16) __half g_whi[16777216];  // [q|k|v|o][2048][2048]
__device__ __align__(16) __half g_qhi[8388608];
__device__ __align__(16) __half g_qlo[8388608];
__device__ __align__(16) __half g_khi[8388608];
__device__ __align__(16) __half g_vhi[8388608];

// ===========================================================================
// fp32 -> fp16 split helpers
// ===========================================================================
__device__ __forceinline__ void split4h(float4 v, __half* hi, __half* lo) {
    __half h0 = __float2half_rn(v.x), h1 = __float2half_rn(v.y);
    __half h2 = __float2half_rn(v.z), h3 = __float2half_rn(v.w);
    __half l0 = __float2half_rn(v.x - __half2float(h0));
    __half l1 = __float2half_rn(v.y - __half2float(h1));
    __half l2 = __float2half_rn(v.z - __half2float(h2));
    __half l3 = __float2half_rn(v.w - __half2float(h3));
    __half2 p;
    p.x = h0; p.y = h1; *(__half2*)(hi)     = p;
    p.x = h2; p.y = h3; *(__half2*)(hi + 2) = p;
    p.x = l0; p.y = l1; *(__half2*)(lo)     = p;
    p.x = l2; p.y = l3; *(__half2*)(lo + 2) = p;
}
__device__ __forceinline__ void cvt4h(float4 v, __half* hi) {
    __half2 p;
    p.x = __float2half_rn(v.x); p.y = __float2half_rn(v.y);
    *(__half2*)(hi) = p;
    p.x = __float2half_rn(v.z); p.y = __float2half_rn(v.w);
    *(__half2*)(hi + 2) = p;
}

// split x -> g_xhi/g_xlo
__global__ void split_x_kernel(const float* __restrict__ x)
{
    int i = (blockIdx.x * 256 + threadIdx.x) * 4;
    split4h(*(const float4*)(x + i), g_xhi + i, g_xlo + i);
}

// W: hi only (the A-side carries the split)
__global__ void split_w_kernel(const float* __restrict__ Wq, const float* __restrict__ Wk,
                               const float* __restrict__ Wv, const float* __restrict__ Wo)
{
    int j = blockIdx.y;
    const float* src = (j == 0) ? Wq : (j == 1) ? Wk : (j == 2) ? Wv : Wo;
    size_t base = (size_t)j * 4194304;
    int i = (blockIdx.x * 256 + threadIdx.x) * 4;
    cvt4h(*(const float4*)(src + i), g_whi + base + i);
}

// v: fp32 -> fp16 (hi only)
__global__ void v_cvt_kernel()
{
    int i = (blockIdx.x * 256 + threadIdx.x) * 4;
    cvt4h(*(const float4*)(g_v + i), g_vhi + i);
}

// ===========================================================================
// Fused RoPE + split: read q,k fp32, rotate, write qhi/qlo/khi (one pass).
// ===========================================================================
__global__ void rope_split_qk_kernel()
{
    int idx = blockIdx.x * 256 + threadIdx.x;
    if (idx >= BB * HH * TT * 64) return;
    int j  = idx & 63;
    int t  = (idx >> 6) & 1023;
    int bh = idx >> 16;
    float inv = exp2f(-(float)j * (13.2877123795f / 64.0f));
    float ang = (float)t * inv;
    float c, s;
    sincosf(ang, &s, &c);
    size_t base = ((size_t)bh * TT + t) * DD + j;

    float q1 = g_q[base], q2 = g_q[base + 64];
    float qa = q1 * c - q2 * s;
    float qb = q2 * c + q1 * s;
    __half ha = __float2half_rn(qa), hb = __float2half_rn(qb);
    g_qhi[base]      = ha;
    g_qhi[base + 64] = hb;
    g_qlo[base]      = __float2half_rn(qa - __half2float(ha));
    g_qlo[base + 64] = __float2half_rn(qb - __half2float(hb));

    float k1 = g_k[base], k2 = g_k[base + 64];
    g_khi[base]      = __float2half_rn(k1 * c - k2 * s);
    g_khi[base + 64] = __float2half_rn(k2 * c + k1 * s);
}

// ===========================================================================
// LoRA left factor. mode 0: U = x @ dA^T (48 cols), mode 1: Uo = y @ doA^T
// ===========================================================================
__global__ void lora_u_kernel(const float* __restrict__ x,
                              const float* __restrict__ delta, int mode)
{
    int bt = blockIdx.x;
    int b  = bt >> 10;
    const float* src  = (mode == 0) ? x : (const float*)g_y;
    const float* xrow = src + (size_t)bt * CC;
    float* dst = (mode == 0) ? g_u : g_uo;
    int nOut   = (mode == 0) ? 48 : 16;

    int lane = threadIdx.x & 31, w = threadIdx.x >> 5;
    for (int j = w; j < nOut; j += 8) {
        int row = (mode == 0) ? ((j >> 4) * 32 + (j & 15)) : (96 + j);
        const float* arow = delta + ((size_t)b * 128 + row) * CC;
        float s = 0.f;
        for (int i = lane * 4; i < CC; i += 128) {
            float4 xv = *(const float4*)(xrow + i);
            float4 av = *(const float4*)(arow + i);
            s += xv.x * av.x + xv.y * av.y + xv.z * av.z + xv.w * av.w;
        }
        #pragma unroll
        for (int o = 16; o; o >>= 1) s += __shfl_xor_sync(0xffffffffu, s, o);
        if (lane == 0) dst[(size_t)bt * nOut + j] = s;
    }
}

// ===========================================================================
// fp16x2 GEMM on mma.sync + cp.async 3-stage pipeline (R13 version, regs=80).
// out = Ah*Bh + Al*Bh. Tile 128x128, K-stage 32, 16 warps (4m x 4n), 512 thr.
// mode 0: QKV -> fp32 head layout (g_q/g_k/g_v). mode 1: O -> outO.
// ===========================================================================
#define MMH_STAGE 30720
#define MMH_SMEM  (3 * MMH_STAGE)

__global__ __launch_bounds__(512, 1)
void mmh_kernel(const float* __restrict__ delta, int mode, float* __restrict__ outO)
{
    extern __shared__ __align__(16) char sm[];
    const int tid = threadIdx.x, lane = tid & 31, wid = tid >> 5;
    const int wm = wid >> 2, wn = wid & 3;
    const int b = blockIdx.z, mt = blockIdx.y, nt = blockIdx.x;
    const int m0 = mt * 128, nbase = nt * 128;
    const int wrow0 = (mode == 0) ? nbase : (6144 + nbase);
    const size_t arow0 = (size_t)b * 1024 + m0;

    const __half* Ahi = (mode == 0) ? g_xhi : g_yhi;
    const __half* Alo = (mode == 0) ? g_xlo : g_ylo;
    const float* Uv = (mode == 0) ? g_u : g_uo;

    const int lrow = tid >> 2, seg = tid & 3;
    const __half* gAh = Ahi + (arow0 + lrow) * 2048 + seg * 8;
    const __half* gAl = Alo + (arow0 + lrow) * 2048 + seg * 8;
    const __half* gBh = g_whi + (size_t)(wrow0 + lrow) * 2048 + seg * 8;
    const uint32_t so = (uint32_t)lrow * 80 + seg * 16;
    const uint32_t sb = smem_u32(sm);

    float acc[2][4][4];
    #pragma unroll
    for (int mi = 0; mi < 2; mi++)
        #pragma unroll
        for (int ni = 0; ni < 4; ni++)
            #pragma unroll
            for (int e = 0; e < 4; e++) acc[mi][ni][e] = 0.f;

    #define MMH_ISSUE(sbase, kt) do { \
        int kk = (kt) * 32; \
        CP_ASYNC16((sbase) + so,         gAh + kk); \
        CP_ASYNC16((sbase) + 10240 + so, gAl + kk); \
        CP_ASYNC16((sbase) + 20480 + so, gBh + kk); \
    } while (0)

    MMH_ISSUE(sb, 0);              CP_COMMIT();
    MMH_ISSUE(sb + MMH_STAGE, 1);  CP_COMMIT();

    const uint32_t aRowBase = (uint32_t)(wm * 32 + (lane & 15)) * 80 + (lane >> 4) * 16;
    const uint32_t bRowBase = (uint32_t)(wn * 32 + (lane & 15)) * 80 + (lane >> 4) * 16;

    int buf = 0, nxt = 2;
    for (int kt = 0; kt < 64; kt++) {
        CP_WAIT1();
        __syncthreads();
        if (kt < 62) MMH_ISSUE(sb + nxt * MMH_STAGE, kt + 2);
        CP_COMMIT();

        uint32_t sA = sb + buf * MMH_STAGE;
        uint32_t sB = sA + 20480;
        #pragma unroll
        for (int ks = 0; ks < 2; ks++) {
            uint32_t ah[2][4], al[2][4], bh[4][2];
            #pragma unroll
            for (int mi = 0; mi < 2; mi++) {
                uint32_t ad = sA + aRowBase + mi * (16 * 80) + ks * 32;
                LDSM_X4(ah[mi], ad);
                LDSM_X4(al[mi], ad + 10240);
            }
            #pragma unroll
            for (int g = 0; g < 2; g++) {
                uint32_t bd = sB + bRowBase + g * (16 * 80) + ks * 32;
                uint32_t t[4];
                LDSM_X4(t, bd);
                bh[g * 2][0] = t[0];  bh[g * 2][1] = t[2];
                bh[g * 2 + 1][0] = t[1]; bh[g * 2 + 1][1] = t[3];
            }
            #pragma unroll
            for (int mi = 0; mi < 2; mi++)
                #pragma unroll
                for (int ni = 0; ni < 4; ni++) {
                    MMA_FP16(acc[mi][ni], ah[mi], bh[ni]);
                    MMA_FP16(acc[mi][ni], al[mi], bh[ni]);
                }
        }
        buf = (buf == 2) ? 0 : buf + 1;
        nxt = (nxt == 2) ? 0 : nxt + 1;
    }
    CP_WAIT0();
    __syncthreads();

    // ---- LoRA epilogue + writeback (R13 form) ----
    float* sU  = (float*)sm;               // [128][17]
    float* sDb = (float*)(sm + 12288);     // [16][136]
    const int seg2    = (mode == 0) ? (nbase >> 11) : 3;
    const int ncol0   = (mode == 0) ? (nbase & 2047) : nbase;
    const int dbrow   = (mode == 0) ? (seg2 * 32 + 16) : 112;
    const int ustride = (mode == 0) ? 48 : 16;
    const int uoff    = (mode == 0) ? seg2 * 16 : 0;

    if (tid < 128) {
        const float* up = Uv + ((size_t)b * 1024 + m0 + tid) * ustride + uoff;
        #pragma unroll
        for (int i = 0; i < 4; i++) {
            float4 v = *(const float4*)(up + i * 4);
            sU[tid * 17 + i * 4 + 0] = v.x;
            sU[tid * 17 + i * 4 + 1] = v.y;
            sU[tid * 17 + i * 4 + 2] = v.z;
            sU[tid * 17 + i * 4 + 3] = v.w;
        }
    }
    {
        int r = tid >> 5, c4 = (tid & 31) * 4;
        float4 v = *(const float4*)(delta + ((size_t)b * 128 + dbrow + r) * 2048 + ncol0 + c4);
        *(float4*)(sDb + r * 136 + c4) = v;
    }
    __syncthreads();

    const int trow = lane >> 2;
    const int tcol = (lane & 3) * 2;
    float* qkvbase = (seg2 == 0) ? g_q : (seg2 == 1) ? g_k : g_v;

    #pragma unroll
    for (int mi = 0; mi < 2; mi++) {
        int lr0 = wm * 32 + mi * 16 + trow;
        int lr1 = lr0 + 8;
        #pragma unroll
        for (int r = 0; r < 16; r++) {
            float u0 = sU[lr0 * 17 + r];
            float u1 = sU[lr1 * 17 + r];
            #pragma unroll
            for (int ni = 0; ni < 4; ni++) {
                int c = wn * 32 + ni * 8 + tcol;
                float d0 = sDb[r * 136 + c];
                float d1 = sDb[r * 136 + c + 1];
                acc[mi][ni][0] += u0 * d0;
                acc[mi][ni][1] += u0 * d1;
                acc[mi][ni][2] += u1 * d0;
                acc[mi][ni][3] += u1 * d1;
            }
        }
        #pragma unroll
        for (int ni = 0; ni < 4; ni++) {
            int c = wn * 32 + ni * 8 + tcol;
            if (mode == 0) {
                int h = ncol0 >> 7;
                float* dst = qkvbase + (((size_t)b * 16 + h) * 1024 + m0) * 128;
                *(float2*)(dst + (size_t)lr0 * 128 + c) = make_float2(acc[mi][ni][0], acc[mi][ni][1]);
                *(float2*)(dst + (size_t)lr1 * 128 + c) = make_float2(acc[mi][ni][2], acc[mi][ni][3]);
            } else {
                float* dst = outO + ((size_t)b * 1024 + m0) * 2048 + nbase;
                *(float2*)(dst + (size_t)lr0 * 2048 + c) = make_float2(acc[mi][ni][0], acc[mi][ni][1]);
                *(float2*)(dst + (size_t)lr1 * 2048 + c) = make_float2(acc[mi][ni][2], acc[mi][ni][3]);
            }
        }
    }
}

// ===========================================================================
// HMMA flash attention, fp16x2. Writes y fp32 + yhi/ylo (fused split).
// ===========================================================================
#define AT_PITCH 272
#define AT_QH 0
#define AT_QL 34816
#define AT_KH 69632
#define AT_VH 104448
#define AT_SMEM 139264

__device__ __forceinline__ void split_pack_h(float x, float y, uint32_t& hi, uint32_t& lo)
{
    __half hx = __float2half_rn(x), hy = __float2half_rn(y);
    __half lx = __float2half_rn(x - __half2float(hx));
    __half ly = __float2half_rn(y - __half2float(hy));
    __half2 h; h.x = hx; h.y = hy;
    __half2 l; l.x = lx; l.y = ly;
    hi = *(uint32_t*)&h;
    lo = *(uint32_t*)&l;
}

__global__ __launch_bounds__(256, 1) void attn_h_kernel()
{
    extern __shared__ __align__(16) char sm[];
    const int tid = threadIdx.x, lane = tid & 31, wid = tid >> 5;
    const int qt = blockIdx.x, bh = blockIdx.y;
    const int q0 = qt * 128;
    const size_t tbase = (size_t)bh * 1024;
    const uint32_t sb = smem_u32(sm);

    #pragma unroll
    for (int i = 0; i < 8; i++) {
        int s = tid + i * 256;
        int row = s >> 4, c = s & 15;
        uint32_t off = (uint32_t)row * AT_PITCH + c * 16;
        size_t g = (tbase + q0 + row) * 128 + c * 8;
        *(uint4*)(sm + AT_QH + off) = *(const uint4*)(g_qhi + g);
        *(uint4*)(sm + AT_QL + off) = *(const uint4*)(g_qlo + g);
    }

    const int gq = lane >> 2, t4 = lane & 3;
    const uint32_t ldRow = (uint32_t)(lane & 15) * AT_PITCH + (lane >> 4) * 16;
    const uint32_t qBase = sb + AT_QH + (uint32_t)(wid * 16) * AT_PITCH + ldRow;

    float o[16][4];
    #pragma unroll
    for (int n = 0; n < 16; n++)
        #pragma unroll
        for (int e = 0; e < 4; e++) o[n][e] = 0.f;
    float mA = -3.0e38f, mB = -3.0e38f, lA = 0.f, lB = 0.f;
    const float scale = 0.08838834764831845f;

    for (int kt = 0; kt < 8; kt++) {
        #pragma unroll
        for (int i = 0; i < 8; i++) {
            int s = tid + i * 256;
            int row = s >> 4, c = s & 15;
            uint32_t off = (uint32_t)row * AT_PITCH + c * 16;
            size_t g = (tbase + kt * 128 + row) * 128 + c * 8;
            *(uint4*)(sm + AT_KH + off) = *(const uint4*)(g_khi + g);
            *(uint4*)(sm + AT_VH + off) = *(const uint4*)(g_vhi + g);
        }
        __syncthreads();

        float s[16][4];
        #pragma unroll
        for (int n = 0; n < 16; n++)
            #pragma unroll
            for (int e = 0; e < 4; e++) s[n][e] = 0.f;

        #pragma unroll
        for (int ks = 0; ks < 8; ks++) {
            uint32_t qh[4], ql[4];
            LDSM_X4(qh, qBase + ks * 32);
            LDSM_X4(ql, qBase + (AT_QL - AT_QH) + ks * 32);
            #pragma unroll
            for (int np = 0; np < 8; np++) {
                uint32_t th[4];
                uint32_t ka = sb + AT_KH + ldRow + np * (16 * AT_PITCH) + ks * 32;
                LDSM_X4(th, ka);
                uint32_t b0h[2] = {th[0], th[2]}, b1h[2] = {th[1], th[3]};
                MMA_FP16(s[2 * np],     qh, b0h);
                MMA_FP16(s[2 * np],     ql, b0h);
                MMA_FP16(s[2 * np + 1], qh, b1h);
                MMA_FP16(s[2 * np + 1], ql, b1h);
            }
        }

        float mxA = -3.0e38f, mxB = -3.0e38f;
        #pragma unroll
        for (int n = 0; n < 16; n++) {
            mxA = fmaxf(mxA, fmaxf(s[n][0], s[n][1]));
            mxB = fmaxf(mxB, fmaxf(s[n][2], s[n][3]));
        }
        mxA = fmaxf(mxA, __shfl_xor_sync(0xffffffffu, mxA, 1));
        mxA = fmaxf(mxA, __shfl_xor_sync(0xffffffffu, mxA, 2));
        mxB = fmaxf(mxB, __shfl_xor_sync(0xffffffffu, mxB, 1));
        mxB = fmaxf(mxB, __shfl_xor_sync(0xffffffffu, mxB, 2));
        float nmA = fmaxf(mA, mxA * scale);
        float nmB = fmaxf(mB, mxB * scale);
        float aA = __expf(mA - nmA), aB = __expf(mB - nmB);
        mA = nmA; mB = nmB;
        float sumA = 0.f, sumB = 0.f;
        #pragma unroll
        for (int n = 0; n < 16; n++) {
            s[n][0] = __expf(s[n][0] * scale - mA); sumA += s[n][0];
            s[n][1] = __expf(s[n][1] * scale - mA); sumA += s[n][1];
            s[n][2] = __expf(s[n][2] * scale - mB); sumB += s[n][2];
            s[n][3] = __expf(s[n][3] * scale - mB); sumB += s[n][3];
        }
        sumA += __shfl_xor_sync(0xffffffffu, sumA, 1);
        sumA += __shfl_xor_sync(0xffffffffu, sumA, 2);
        sumB += __shfl_xor_sync(0xffffffffu, sumB, 1);
        sumB += __shfl_xor_sync(0xffffffffu, sumB, 2);
        lA = lA * aA + sumA;
        lB = lB * aB + sumB;
        #pragma unroll
        for (int n = 0; n < 16; n++) {
            o[n][0] *= aA; o[n][1] *= aA;
            o[n][2] *= aB; o[n][3] *= aB;
        }

        #pragma unroll
        for (int kk = 0; kk < 8; kk++) {
            uint32_t ph[4], pl[4];
            split_pack_h(s[2 * kk][0],     s[2 * kk][1],     ph[0], pl[0]);
            split_pack_h(s[2 * kk][2],     s[2 * kk][3],     ph[1], pl[1]);
            split_pack_h(s[2 * kk + 1][0], s[2 * kk + 1][1], ph[2], pl[2]);
            split_pack_h(s[2 * kk + 1][2], s[2 * kk + 1][3], ph[3], pl[3]);
            #pragma unroll
            for (int np = 0; np < 8; np++) {
                uint32_t tv[4];
                uint32_t va = sb + AT_VH + ldRow + kk * (16 * AT_PITCH) + np * 32;
                LDSM_X4_T(tv, va);
                uint32_t b0[2] = {tv[0], tv[1]}, b1[2] = {tv[2], tv[3]};
                MMA_FP16(o[2 * np],     ph, b0);
                MMA_FP16(o[2 * np],     pl, b0);
                MMA_FP16(o[2 * np + 1], ph, b1);
                MMA_FP16(o[2 * np + 1], pl, b1);
            }
        }
        __syncthreads();
    }

    // ---- normalize + write y fp32 and yhi/ylo (fused split) ----
    int b = bh >> 4, h = bh & 15;
    float iA = 1.f / lA, iB = 1.f / lB;
    int rA = q0 + wid * 16 + gq, rB = rA + 8;
    size_t offA = ((size_t)b * TT + rA) * CC + h * 128;
    size_t offB = ((size_t)b * TT + rB) * CC + h * 128;
    #pragma unroll
    for (int n = 0; n < 16; n++) {
        int d = n * 8 + t4 * 2;
        float a0 = o[n][0] * iA, a1 = o[n][1] * iA;
        float b0 = o[n][2] * iB, b1 = o[n][3] * iB;
        *(float2*)(g_y + offA + d) = make_float2(a0, a1);
        *(float2*)(g_y + offB + d) = make_float2(b0, b1);
        uint32_t hA, lA2, hB, lB2;
        split_pack_h(a0, a1, hA, lA2);
        split_pack_h(b0, b1, hB, lB2);
        *(uint32_t*)(g_yhi + offA + d) = hA;
        *(uint32_t*)(g_ylo + offA + d) = lA2;
        *(uint32_t*)(g_yhi + offB + d) = hB;
        *(uint32_t*)(g_ylo + offB + d) = lB2;
    }
}

// ===========================================================================
extern "C" void kernel_launch(void* const* d_in, const int* in_sizes, int n_in,
                              void* d_out, int out_size)
{
    const float* x     = (const float*)d_in[0];
    const float* delta = (const float*)d_in[1];
    const float* Wq    = (const float*)d_in[2];
    const float* Wk    = (const float*)d_in[3];
    const float* Wv    = (const float*)d_in[4];
    const float* Wo    = (const float*)d_in[5];
    float* out = (float*)d_out;

    cudaFuncSetAttribute(mmh_kernel, cudaFuncAttributeMaxDynamicSharedMemorySize,
                         MMH_SMEM);
    cudaFuncSetAttribute(attn_h_kernel, cudaFuncAttributeMaxDynamicSharedMemorySize,
                         AT_SMEM);

    split_w_kernel<<<dim3(4096, 4), 256>>>(Wq, Wk, Wv, Wo);
    split_x_kernel<<<8192, 256>>>(x);
    lora_u_kernel<<<BB * TT, 256>>>(x, delta, 0);
    mmh_kernel<<<dim3(48, 8, BB), 512, MMH_SMEM>>>(delta, 0, nullptr);
    rope_split_qk_kernel<<<(BB * HH * TT * 64) / 256, 256>>>();
    v_cvt_kernel<<<8192, 256>>>();
    attn_h_kernel<<<dim3(8, BB * HH), 256, AT_SMEM>>>();
    lora_u_kernel<<<BB * TT, 256>>>(x, delta, 1);
    mmh_kernel<<<dim3(16, 8, BB), 512, MMH_SMEM>>>(delta, 1, out);
}